// round 15
// baseline (speedup 1.0000x reference)
#include <cuda_runtime.h>

// Problem constants (fixed by setup_inputs)
#define F_DIM    16384
#define BINS     128
#define FEAT     (2*BINS + 1)     // 257
#define OUT_DIM  64

#define NTHREADS 512
#define NWARPS   (NTHREADS/32)    // 16
#define VPT      (F_DIM/NTHREADS) // 32 values per thread (8 float4)
#define REG_Q    3                // float4 quads kept in registers
#define SM_Q     (VPT/4 - REG_Q)  // 5 float4 quads staged in smem

// smem layout (bytes)
#define STAGE_BYTES (NTHREADS * SM_Q * 16)          // 40960
#define HIST_OFF    STAGE_BYTES
#define FEATS_OFF   (HIST_OFF + NWARPS * BINS * 4)  // +8192
#define MINMAX_OFF  (FEATS_OFF + 260 * 4)
#define SMEM_TOTAL  (MINMAX_OFF + 2 * NWARPS * 4)

extern __shared__ unsigned char smem_raw[];

// Fused: per-row histogram features + out[row] = feats . W^T + b.
// One block per row. 3 blocks/SM (launch_bounds(512,3)): register pressure cut
// by staging 20 of 32 per-thread values in smem across the min/max sync, the
// other 12 stay in registers. W read via LDG, L1-resident across blocks.
__global__ __launch_bounds__(NTHREADS, 3)
void hist_fused_kernel(const float* __restrict__ x,
                       const float* __restrict__ W,
                       const float* __restrict__ bias,
                       float* __restrict__ out)
{
    float4* s_stage = (float4*)smem_raw;                        // 512*5 float4
    int*    s_hist  = (int*)(smem_raw + HIST_OFF);              // 16*128 ints
    float*  s_feats = (float*)(smem_raw + FEATS_OFF);           // 257 (pad 260)
    float*  s_wmin  = (float*)(smem_raw + MINMAX_OFF);
    float*  s_wmax  = s_wmin + NWARPS;

    const int t    = threadIdx.x;
    const int wid  = t >> 5;
    const int lane = t & 31;
    const int row  = blockIdx.x;

    // zero per-warp histograms
    #pragma unroll
    for (int i = t; i < NWARPS * BINS; i += NTHREADS) s_hist[i] = 0;

    // Pass A: stream row HBM; first REG_Q quads stay in regs, rest -> smem
    const float4* xr = (const float4*)(x + (size_t)row * F_DIM);
    float lmin =  3.402823e38f;
    float lmax = -3.402823e38f;
    float4 v[REG_Q];
    #pragma unroll
    for (int k = 0; k < REG_Q; k++) {
        v[k] = xr[t + k * NTHREADS];
        lmin = fminf(lmin, fminf(fminf(v[k].x, v[k].y), fminf(v[k].z, v[k].w)));
        lmax = fmaxf(lmax, fmaxf(fmaxf(v[k].x, v[k].y), fmaxf(v[k].z, v[k].w)));
    }
    #pragma unroll
    for (int k = 0; k < SM_Q; k++) {
        float4 u = xr[t + (REG_Q + k) * NTHREADS];
        s_stage[t + k * NTHREADS] = u;
        lmin = fminf(lmin, fminf(fminf(u.x, u.y), fminf(u.z, u.w)));
        lmax = fmaxf(lmax, fmaxf(fmaxf(u.x, u.y), fmaxf(u.z, u.w)));
    }
    // warp reduce min/max
    #pragma unroll
    for (int s = 16; s; s >>= 1) {
        lmin = fminf(lmin, __shfl_xor_sync(0xffffffffu, lmin, s));
        lmax = fmaxf(lmax, __shfl_xor_sync(0xffffffffu, lmax, s));
    }
    if (lane == 0) { s_wmin[wid] = lmin; s_wmax[wid] = lmax; }
    __syncthreads();

    // block min/max
    float mn = s_wmin[0], mx = s_wmax[0];
    #pragma unroll
    for (int i = 1; i < NWARPS; i++) {
        mn = fminf(mn, s_wmin[i]);
        mx = fmaxf(mx, s_wmax[i]);
    }
    const float width = mx - mn;
    const float scale = (width > 0.0f) ? ((float)BINS / width) : 0.0f;
    const float base  = -mn * scale;   // bin = (int)fmaf(v, scale, base)

    // Pass B: histogram; register quads first, then staged quads from smem
    int* hw = s_hist + wid * BINS;
    #pragma unroll
    for (int k = 0; k < REG_Q; k++) {
        int b0 = min(BINS - 1, (int)fmaf(v[k].x, scale, base));
        int b1 = min(BINS - 1, (int)fmaf(v[k].y, scale, base));
        int b2 = min(BINS - 1, (int)fmaf(v[k].z, scale, base));
        int b3 = min(BINS - 1, (int)fmaf(v[k].w, scale, base));
        atomicAdd(&hw[b0], 1);
        atomicAdd(&hw[b1], 1);
        atomicAdd(&hw[b2], 1);
        atomicAdd(&hw[b3], 1);
    }
    #pragma unroll
    for (int k = 0; k < SM_Q; k++) {
        float4 u = s_stage[t + k * NTHREADS];
        int b0 = min(BINS - 1, (int)fmaf(u.x, scale, base));
        int b1 = min(BINS - 1, (int)fmaf(u.y, scale, base));
        int b2 = min(BINS - 1, (int)fmaf(u.z, scale, base));
        int b3 = min(BINS - 1, (int)fmaf(u.w, scale, base));
        atomicAdd(&hw[b0], 1);
        atomicAdd(&hw[b1], 1);
        atomicAdd(&hw[b2], 1);
        atomicAdd(&hw[b3], 1);
    }
    __syncthreads();

    // reduce per-warp histograms + emit feats row into SMEM
    if (t < BINS) {
        int c = 0;
        #pragma unroll
        for (int w = 0; w < NWARPS; w++) c += s_hist[w * BINS + t];
        s_feats[t] = (float)c * (1.0f / (float)F_DIM);   // density: sum == F exactly
    } else if (t < BINS + BINS + 1) {
        int i = t - BINS;
        s_feats[BINS + i] = mn + ((float)i * (1.0f / (float)BINS)) * width;
    }
    __syncthreads();

    // ---- fused GEMM tail: out[row][c] = feats . W[c] + bias[c] ----
    // warp wid handles cols 4*wid..4*wid+3; lanes split k = lane + 32j.
    // Register-lean: col loop rolled, operands re-read each iter.
    #pragma unroll 1
    for (int cc = 0; cc < 4; cc++) {
        const int c = wid * 4 + cc;
        const float* wr = W + (size_t)c * FEAT;
        float acc = 0.0f;
        #pragma unroll
        for (int j = 0; j < 8; j++)
            acc = fmaf(s_feats[lane + 32 * j], __ldg(wr + lane + 32 * j), acc);
        if (lane == 0) acc = fmaf(s_feats[256], __ldg(wr + 256), acc);
        // warp reduce (fixed order -> deterministic)
        #pragma unroll
        for (int s = 16; s; s >>= 1)
            acc += __shfl_xor_sync(0xffffffffu, acc, s);
        if (lane == 0)
            out[(size_t)row * OUT_DIM + c] = acc + __ldg(bias + c);
    }
}

extern "C" void kernel_launch(void* const* d_in, const int* in_sizes, int n_in,
                              void* d_out, int out_size)
{
    const float* x = (const float*)d_in[0];
    const float* W = (const float*)d_in[1];
    const float* b = (const float*)d_in[2];
    float* out = (float*)d_out;

    const int B = in_sizes[0] / F_DIM;

    cudaFuncSetAttribute(hist_fused_kernel,
                         cudaFuncAttributeMaxDynamicSharedMemorySize, SMEM_TOTAL);

    hist_fused_kernel<<<B, NTHREADS, SMEM_TOTAL>>>(x, W, b, out);
}

// round 17
// speedup vs baseline: 1.0241x; 1.0241x over previous
#include <cuda_runtime.h>

// Problem constants (fixed by setup_inputs)
#define F_DIM    16384
#define BINS     128
#define FEAT     (2*BINS + 1)     // 257
#define OUT_DIM  64

#define NTHREADS 512
#define NWARPS   (NTHREADS/32)    // 16
#define VPT      (F_DIM/NTHREADS) // 32 values per thread (8 float4)

// Precomputed boundary-half sums: S1[c] = sum_i W[c][128+i],
// S2[c] = sum_i (i/128) * W[c][128+i].  (W-only; computed per replay.)
__device__ float g_S1[OUT_DIM];
__device__ float g_S2[OUT_DIM];

extern __shared__ unsigned char smem_raw[];

// ---- prep kernel: 1 block, 256 threads; warp w -> cols w*8..w*8+7 ----
__global__ __launch_bounds__(256)
void prep_kernel(const float* __restrict__ W)
{
    const int wid  = threadIdx.x >> 5;
    const int lane = threadIdx.x & 31;
    #pragma unroll 1
    for (int cc = 0; cc < 8; cc++) {
        const int c = wid * 8 + cc;
        const float* wb = W + (size_t)c * FEAT + BINS;   // 129 values
        float s1 = 0.f, s2 = 0.f;
        #pragma unroll
        for (int j = 0; j < 5; j++) {
            const int i = lane + 32 * j;
            if (i < BINS + 1) {
                float w = __ldg(wb + i);
                s1 += w;
                s2 = fmaf((float)i * (1.0f / (float)BINS), w, s2);
            }
        }
        #pragma unroll
        for (int s = 16; s; s >>= 1) {
            s1 += __shfl_xor_sync(0xffffffffu, s1, s);
            s2 += __shfl_xor_sync(0xffffffffu, s2, s);
        }
        if (lane == 0) { g_S1[c] = s1; g_S2[c] = s2; }
    }
}

// ---- fused: per-row histogram + out[row][c] = counts.Wc + mn*S1 + width*S2 + b ----
// One block per row. R11's proven hist body (all values register-resident,
// per-warp privatized smem histograms). Tail is tiny: 128-MAC dot product on
// the counts half only; boundary half folded into 2 FMAs via g_S1/g_S2.
__global__ __launch_bounds__(NTHREADS)
void hist_fused_kernel(const float* __restrict__ x,
                       const float* __restrict__ W,
                       const float* __restrict__ bias,
                       float* __restrict__ out)
{
    int*   s_hist   = (int*)smem_raw;                                  // 16*128*4 = 8192 B
    float* s_counts = (float*)(smem_raw + (size_t)NWARPS * BINS * 4);  // 128 f
    float* s_wmin   = s_counts + BINS;
    float* s_wmax   = s_wmin + NWARPS;

    const int t    = threadIdx.x;
    const int wid  = t >> 5;
    const int lane = t & 31;
    const int row  = blockIdx.x;

    // zero per-warp histograms
    #pragma unroll
    for (int i = t; i < NWARPS * BINS; i += NTHREADS) s_hist[i] = 0;

    // Pass A: stream row HBM -> registers (float4), track min/max in flight
    const float4* xr = (const float4*)(x + (size_t)row * F_DIM);
    float4 v[VPT / 4];
    float lmin =  3.402823e38f;
    float lmax = -3.402823e38f;
    #pragma unroll
    for (int k = 0; k < VPT / 4; k++) {
        v[k] = xr[t + k * NTHREADS];
        lmin = fminf(lmin, fminf(fminf(v[k].x, v[k].y), fminf(v[k].z, v[k].w)));
        lmax = fmaxf(lmax, fmaxf(fmaxf(v[k].x, v[k].y), fmaxf(v[k].z, v[k].w)));
    }
    // warp reduce min/max
    #pragma unroll
    for (int s = 16; s; s >>= 1) {
        lmin = fminf(lmin, __shfl_xor_sync(0xffffffffu, lmin, s));
        lmax = fmaxf(lmax, __shfl_xor_sync(0xffffffffu, lmax, s));
    }
    if (lane == 0) { s_wmin[wid] = lmin; s_wmax[wid] = lmax; }
    __syncthreads();

    // block min/max (every thread computes; mn/width stay in registers)
    float mn = s_wmin[0], mx = s_wmax[0];
    #pragma unroll
    for (int i = 1; i < NWARPS; i++) {
        mn = fminf(mn, s_wmin[i]);
        mx = fmaxf(mx, s_wmax[i]);
    }
    const float width = mx - mn;
    const float scale = (width > 0.0f) ? ((float)BINS / width) : 0.0f;
    const float base  = -mn * scale;   // bin = (int)fmaf(v, scale, base)

    // Pass B: histogram straight from registers, per-warp privatized counters
    int* hw = s_hist + wid * BINS;
    #pragma unroll
    for (int k = 0; k < VPT / 4; k++) {
        int b0 = min(BINS - 1, (int)fmaf(v[k].x, scale, base));
        int b1 = min(BINS - 1, (int)fmaf(v[k].y, scale, base));
        int b2 = min(BINS - 1, (int)fmaf(v[k].z, scale, base));
        int b3 = min(BINS - 1, (int)fmaf(v[k].w, scale, base));
        atomicAdd(&hw[b0], 1);
        atomicAdd(&hw[b1], 1);
        atomicAdd(&hw[b2], 1);
        atomicAdd(&hw[b3], 1);
    }
    __syncthreads();

    // reduce per-warp histograms -> normalized counts in smem
    if (t < BINS) {
        int c = 0;
        #pragma unroll
        for (int w = 0; w < NWARPS; w++) c += s_hist[w * BINS + t];
        s_counts[t] = (float)c * (1.0f / (float)F_DIM);   // density: sum == F exactly
    }
    __syncthreads();

    // ---- tiny fused tail: warp wid -> cols 4*wid..4*wid+3 ----
    // counts half: lanes split k = lane + 32j (j<4), W via LDG (L1-resident);
    // boundary half: mn*S1[c] + width*S2[c].
    #pragma unroll 1
    for (int cc = 0; cc < 4; cc++) {
        const int c = wid * 4 + cc;
        const float* wc = W + (size_t)c * FEAT;
        float acc = 0.0f;
        #pragma unroll
        for (int j = 0; j < 4; j++)
            acc = fmaf(s_counts[lane + 32 * j], __ldg(wc + lane + 32 * j), acc);
        #pragma unroll
        for (int s = 16; s; s >>= 1)
            acc += __shfl_xor_sync(0xffffffffu, acc, s);
        if (lane == 0) {
            acc = fmaf(mn,    g_S1[c], acc);
            acc = fmaf(width, g_S2[c], acc);
            out[(size_t)row * OUT_DIM + c] = acc + __ldg(bias + c);
        }
    }
}

extern "C" void kernel_launch(void* const* d_in, const int* in_sizes, int n_in,
                              void* d_out, int out_size)
{
    const float* x = (const float*)d_in[0];
    const float* W = (const float*)d_in[1];
    const float* b = (const float*)d_in[2];
    float* out = (float*)d_out;

    const int B = in_sizes[0] / F_DIM;

    // smem: hist 8192 + counts 128*4 + minmax 2*16*4 = 8832 B
    const size_t sm = (size_t)NWARPS * BINS * 4 + BINS * 4 + 2 * NWARPS * 4;

    cudaFuncSetAttribute(hist_fused_kernel,
                         cudaFuncAttributeMaxDynamicSharedMemorySize, (int)sm);

    prep_kernel<<<1, 256>>>(W);
    hist_fused_kernel<<<B, NTHREADS, sm>>>(x, W, b, out);
}